// round 9
// baseline (speedup 1.0000x reference)
#include <cuda_runtime.h>

// LearnedBFGSSolver, 3-kernel pipeline:
//  K1 kz: U0 = H0*Y, V0 = H0^T*Y for all 3072 (be,t) rows.
//         Thread = column i computes BOTH U and V (Y read once); Y distributed
//         from registers via warp shuffle (no per-j LDS broadcast).
//  K2 ks: per-pair Grams -> 12x12 scalar recursion -> factor vectors A, Un.
//  K3 ke: H = H0 + S^T A + Un^T S (rank-24 GEMM), bank-conflict-free layout.

#define NN 192
#define TT 12
#define BE 256
#define KZROWS 12
#define KZPAIRS 6

typedef unsigned long long u64;

__device__ float g_U0[BE * TT * NN];   // u0_t = H0 y_t
__device__ float g_V0[BE * TT * NN];   // v0_t = H0^T y_t
__device__ float g_A [BE * TT * NN];   // A[k][j]  = c1_k s_kj - c2_k v_kj
__device__ float g_Un[BE * TT * NN];   // Un[k][i] = -c2_k u_ki

__device__ __forceinline__ u64 fma2(u64 a, u64 b, u64 c) {
    u64 d; asm("fma.rn.f32x2 %0, %1, %2, %3;" : "=l"(d) : "l"(a), "l"(b), "l"(c));
    return d;
}
__device__ __forceinline__ u64 pack2(float lo, float hi) {
    u64 d; asm("mov.b64 %0, {%1, %2};" : "=l"(d) : "f"(lo), "f"(hi));
    return d;
}
__device__ __forceinline__ void unpack2(u64 v, float& lo, float& hi) {
    asm("mov.b64 {%0, %1}, %2;" : "=f"(lo), "=f"(hi) : "l"(v));
}

// ---------------- K1: batched H0*y and H0^T*y ----------------
// grid 256 (12 rows = 6 packed pairs per CTA), 192 threads (thread = column i).
struct KzSmem {
    u64   Yp[NN][7];       // Yp[j][p], p<6; row padded to 56B -> 2-way max  10752 B
    float st[NN][33];      // st[i][jj] = H0[i][j0+jj]  (row view, padded)   25344 B
    float t2[32][NN];      // t2[jj][i] = H0[j0+jj][i]  (col view)           24576 B
};

__global__ void __launch_bounds__(192)
kz_kernel(const float* __restrict__ H0g, const float* __restrict__ dgs)
{
    extern __shared__ char kz_raw[];
    KzSmem* sm = reinterpret_cast<KzSmem*>(kz_raw);
    const int tid  = threadIdx.x;
    const int lane = tid & 31;
    const int r0   = blockIdx.x * KZROWS;   // even-aligned: pairs never wrap be

    // Stage packed Y once: thread = j
    #pragma unroll
    for (int p = 0; p < KZPAIRS; p++) {
        float lo = dgs[(size_t)(r0 + 2 * p) * NN + tid];
        float hi = dgs[(size_t)(r0 + 2 * p + 1) * NN + tid];
        sm->Yp[tid][p] = pack2(lo, hi);
    }

    const int i = tid;
    u64 accU[KZPAIRS], accV[KZPAIRS];
    #pragma unroll
    for (int p = 0; p < KZPAIRS; p++) { accU[p] = 0ull; accV[p] = 0ull; }

    for (int jt = 0; jt < 6; jt++) {
        const int j0 = jt * 32;
        __syncthreads();   // (also orders Yp staging on first iteration)
        // t2 tile: H0[j0:j0+32][0:192], float4 coalesced (1536 float4 / 192 thr)
        #pragma unroll
        for (int n = 0; n < 8; n++) {
            int idx = n * 192 + tid;
            int row = idx / 48, c4 = (idx % 48) * 4;
            *(float4*)&sm->t2[row][c4] =
                *(const float4*)&H0g[(size_t)(j0 + row) * NN + c4];
        }
        // st tile: H0[0:192][j0:j0+32], scalar coalesced (6144 / 192 thr)
        #pragma unroll
        for (int n = 0; n < 32; n++) {
            int e = n * 192 + tid;
            int r = e >> 5, jj = e & 31;
            sm->st[r][jj] = H0g[(size_t)r * NN + j0 + jj];
        }
        __syncthreads();

        // Per-lane Y preload for this tile: lane jl owns j = j0 + jl
        u64 yreg[KZPAIRS];
        #pragma unroll
        for (int p = 0; p < KZPAIRS; p++) yreg[p] = sm->Yp[j0 + lane][p];

        #pragma unroll 8
        for (int jj = 0; jj < 32; jj++) {
            float h  = sm->st[i][jj];          // H0[i][j]  -> U0
            float hc = sm->t2[jj][i];          // H0[j][i]  -> V0
            u64 h2  = pack2(h, h);
            u64 hc2 = pack2(hc, hc);
            #pragma unroll
            for (int p = 0; p < KZPAIRS; p++) {
                u64 y2 = __shfl_sync(0xFFFFFFFFu, yreg[p], jj);
                accU[p] = fma2(h2,  y2, accU[p]);
                accV[p] = fma2(hc2, y2, accV[p]);
            }
        }
    }

    #pragma unroll
    for (int p = 0; p < KZPAIRS; p++) {
        int r = r0 + 2 * p;                 // even -> pair shares t, be+1 <= 255
        int t = r / BE, be = r % BE;
        float ulo, uhi, vlo, vhi;
        unpack2(accU[p], ulo, uhi);
        unpack2(accV[p], vlo, vhi);
        g_U0[((size_t)be * TT + t) * NN + i]       = ulo;
        g_U0[((size_t)(be + 1) * TT + t) * NN + i] = uhi;
        g_V0[((size_t)be * TT + t) * NN + i]       = vlo;
        g_V0[((size_t)(be + 1) * TT + t) * NN + i] = vhi;
    }
}

// ---------------- K2: per-pair scalar recursion + factor vectors ----------------
__global__ void __launch_bounds__(192)
ks_kernel(const float* __restrict__ steps, const float* __restrict__ dgs)
{
    __shared__ float sS[TT][NN], sY[TT][NN], sU0[TT][NN], sV0[TT][NN];
    __shared__ float sG1[TT][TT], sW[TT][TT];
    __shared__ float sCU[TT][TT], sCV[TT][TT], sB[TT][TT];
    __shared__ float sC1[TT], sC2[TT];

    const int tid = threadIdx.x;
    const int be  = blockIdx.x;

    for (int idx = tid; idx < TT * NN / 4; idx += 192) {
        int e = idx * 4;
        int k = e / NN, j = e % NN;
        *(float4*)&sS[k][j]  = *(const float4*)&steps[(size_t)(k * BE + be) * NN + j];
        *(float4*)&sY[k][j]  = *(const float4*)&dgs  [(size_t)(k * BE + be) * NN + j];
        *(float4*)&sU0[k][j] = *(const float4*)&g_U0[(size_t)(be * TT + k) * NN + j];
        *(float4*)&sV0[k][j] = *(const float4*)&g_V0[(size_t)(be * TT + k) * NN + j];
    }
    __syncthreads();

    // Grams: G1 = S Y^T, W = V0 Y^T  (2x2 cells per thread, 72 threads)
    if (tid < 72) {
        int which = tid / 36;
        int cell  = tid % 36;
        int k0 = (cell / 6) * 2, t0 = (cell % 6) * 2;
        const float (*P)[NN] = which ? sV0 : sS;
        float a00 = 0.f, a01 = 0.f, a10 = 0.f, a11 = 0.f;
        for (int j = 0; j < NN; j += 4) {
            float4 p0 = *(const float4*)&P[k0][j];
            float4 p1 = *(const float4*)&P[k0 + 1][j];
            float4 q0 = *(const float4*)&sY[t0][j];
            float4 q1 = *(const float4*)&sY[t0 + 1][j];
            a00 += p0.x * q0.x + p0.y * q0.y + p0.z * q0.z + p0.w * q0.w;
            a01 += p0.x * q1.x + p0.y * q1.y + p0.z * q1.z + p0.w * q1.w;
            a10 += p1.x * q0.x + p1.y * q0.y + p1.z * q0.z + p1.w * q0.w;
            a11 += p1.x * q1.x + p1.y * q1.y + p1.z * q1.z + p1.w * q1.w;
        }
        float (*G)[TT] = which ? sW : sG1;
        G[k0][t0] = a00;     G[k0][t0 + 1] = a01;
        G[k0 + 1][t0] = a10; G[k0 + 1][t0 + 1] = a11;
    }
    __syncthreads();

    // Warp-0 scalar recursion, lane = column t
    if (tid < 32) {
        const int t = (tid < TT) ? tid : (TT - 1);
        float G1c[TT], Wc[TT], Wr[TT];
        float d2c[TT], d3c[TT];
        float c1v[TT], c2v[TT];
        float cuL[TT], cvL[TT], bL[TT];
        #pragma unroll
        for (int m = 0; m < TT; m++) {
            G1c[m] = sG1[m][t];
            Wc[m]  = sW[m][t];
            Wr[m]  = sW[t][m];
            cuL[m] = 0.f; cvL[m] = 0.f; bL[m] = 0.f;
        }
        #pragma unroll
        for (int k = 0; k < TT; k++) {
            if (k > 0) {
                const int m = k - 1;
                cuL[m] = c1v[m] * G1c[m] - c2v[m] * d2c[m];
                cvL[m] = c1v[m] * G1c[m] - c2v[m] * d3c[m];
                bL[m]  = -c2v[m] * G1c[m];
            }
            float x2 = Wc[k], x3 = Wr[k];
            #pragma unroll
            for (int m = 0; m < TT - 1; m++) {
                if (m < k) {
                    float cvk = __shfl_sync(0xFFFFFFFFu, cvL[m], k);
                    float cuk = __shfl_sync(0xFFFFFFFFu, cuL[m], k);
                    float bk  = __shfl_sync(0xFFFFFFFFu, bL[m],  k);
                    x2 += cvk * G1c[m] + bk * d2c[m];
                    x3 += cuk * G1c[m] + bk * d3c[m];
                }
            }
            d2c[k] = x2;
            d3c[k] = x3;
            float yHy  = __shfl_sync(0xFFFFFFFFu, x3, k);
            float sdot = __shfl_sync(0xFFFFFFFFu, G1c[k], k);
            float ic = (sdot != 0.0f) ? (1.0f / sdot) : 0.0f;
            c2v[k] = ic;
            c1v[k] = (sdot + yHy) * ic * ic;
        }
        if (tid < TT) {
            #pragma unroll
            for (int m = 0; m < TT - 1; m++) {
                sCU[m][t] = cuL[m];
                sCV[m][t] = cvL[m];
                sB[m][t]  = bL[m];
            }
        }
        if (tid == 0) {
            #pragma unroll
            for (int m = 0; m < TT; m++) { sC1[m] = c1v[m]; sC2[m] = c2v[m]; }
        }
    }
    __syncthreads();

    // Barrier-free per-element rebuild of u_t, v_t; emit A, Un
    {
        const int i = tid;
        float s[TT], u[TT], v[TT];
        #pragma unroll
        for (int k = 0; k < TT; k++) {
            s[k] = sS[k][i];
            u[k] = sU0[k][i];
            v[k] = sV0[k][i];
        }
        #pragma unroll
        for (int t = 0; t < TT; t++) {
            #pragma unroll
            for (int k = 0; k < TT - 1; k++) {
                if (k < t) {
                    float bb = sB[k][t];
                    u[t] += sCU[k][t] * s[k] + bb * u[k];
                    v[t] += sCV[k][t] * s[k] + bb * v[k];
                }
            }
            float c1 = sC1[t], c2 = sC2[t];
            g_A [(size_t)(be * TT + t) * NN + i] = c1 * s[t] - c2 * v[t];
            g_Un[(size_t)(be * TT + t) * NN + i] = -c2 * u[t];
        }
    }
}

// ---------------- K3: rank-24 epilogue GEMM ----------------
// grid = 256 pairs * 3 row-blocks (64 rows); 192 threads; 8x8 f32x2 tiles.
// cg = tid>>3 (8 lanes broadcast one column address), rg = tid&7.
__global__ void __launch_bounds__(192)
ke_kernel(const float* __restrict__ H0g,
          const float* __restrict__ steps,
          float* __restrict__ out)
{
    __shared__ float sA[TT][NN];
    __shared__ float sS[TT][NN];
    __shared__ float sUn[TT][64];
    const int tid  = threadIdx.x;
    const int be   = blockIdx.x / 3;
    const int rblk = (blockIdx.x % 3) * 64;

    for (int idx = tid; idx < TT * NN / 4; idx += 192) {
        int e = idx * 4;
        int k = e / NN, j = e % NN;
        *(float4*)&sA[k][j] = *(const float4*)&g_A[(size_t)(be * TT + k) * NN + j];
        *(float4*)&sS[k][j] = *(const float4*)&steps[(size_t)(k * BE + be) * NN + j];
    }
    {
        int e = tid * 4;               // TT*64/4 = 192 float4 loads, 1/thread
        int k = e / 64, r = e % 64;
        *(float4*)&sUn[k][r] = *(const float4*)&g_Un[(size_t)(be * TT + k) * NN + rblk + r];
    }
    __syncthreads();

    const int cg = tid >> 3, rg = tid & 7;
    const int c0  = cg * 8;
    const int lr0 = rg * 8;
    const int grow = rblk + lr0;
    float* ob = out + (size_t)be * NN * NN;

    u64 acc[8][4];
    #pragma unroll
    for (int r = 0; r < 8; r++) {
        ulonglong2 h01 = *(const ulonglong2*)&H0g[(size_t)(grow + r) * NN + c0];
        ulonglong2 h23 = *(const ulonglong2*)&H0g[(size_t)(grow + r) * NN + c0 + 4];
        acc[r][0] = h01.x; acc[r][1] = h01.y; acc[r][2] = h23.x; acc[r][3] = h23.y;
    }
    #pragma unroll
    for (int k = 0; k < TT; k++) {
        ulonglong2 a01 = *(ulonglong2*)&sA[k][c0];
        ulonglong2 a23 = *(ulonglong2*)&sA[k][c0 + 4];
        ulonglong2 s01 = *(ulonglong2*)&sS[k][c0];
        ulonglong2 s23 = *(ulonglong2*)&sS[k][c0 + 4];
        u64 av[4] = {a01.x, a01.y, a23.x, a23.y};
        u64 sv[4] = {s01.x, s01.y, s23.x, s23.y};
        float4 sr0 = *(float4*)&sS[k][grow];
        float4 sr1 = *(float4*)&sS[k][grow + 4];
        float4 ur0 = *(float4*)&sUn[k][lr0];
        float4 ur1 = *(float4*)&sUn[k][lr0 + 4];
        float srow[8] = {sr0.x, sr0.y, sr0.z, sr0.w, sr1.x, sr1.y, sr1.z, sr1.w};
        float urow[8] = {ur0.x, ur0.y, ur0.z, ur0.w, ur1.x, ur1.y, ur1.z, ur1.w};
        #pragma unroll
        for (int r = 0; r < 8; r++) {
            u64 s2 = pack2(srow[r], srow[r]);
            u64 u2 = pack2(urow[r], urow[r]);
            #pragma unroll
            for (int c = 0; c < 4; c++) {
                acc[r][c] = fma2(s2, av[c], acc[r][c]);
                acc[r][c] = fma2(u2, sv[c], acc[r][c]);
            }
        }
    }
    #pragma unroll
    for (int r = 0; r < 8; r++) {
        *(ulonglong2*)&ob[(size_t)(grow + r) * NN + c0] =
            make_ulonglong2(acc[r][0], acc[r][1]);
        *(ulonglong2*)&ob[(size_t)(grow + r) * NN + c0 + 4] =
            make_ulonglong2(acc[r][2], acc[r][3]);
    }
}

extern "C" void kernel_launch(void* const* d_in, const int* in_sizes, int n_in,
                              void* d_out, int out_size) {
    const float* H0    = (const float*)d_in[0];   // inv_hessian [192,192]
    const float* steps = (const float*)d_in[1];   // [12,8,32,192]
    const float* dgs   = (const float*)d_in[2];   // [12,8,32,192]
    float* out = (float*)d_out;                   // [8,32,192,192]

    int kz_smem = (int)sizeof(KzSmem);
    cudaFuncSetAttribute(kz_kernel,
                         cudaFuncAttributeMaxDynamicSharedMemorySize, kz_smem);
    kz_kernel<<<BE, 192, kz_smem>>>(H0, dgs);
    ks_kernel<<<BE, 192>>>(steps, dgs);
    ke_kernel<<<BE * 3, 192>>>(H0, steps, out);
}

// round 10
// speedup vs baseline: 1.0576x; 1.0576x over previous
#include <cuda_runtime.h>

// LearnedBFGSSolver — single fused kernel, one CTA per (b,e) pair (grid 256).
// P1: U0 = H0 y_t, V0 = H0^T y_t (tiled H0 through SMEM, 2-col x 6-pair x 2-side
//     register tiles, j split in halves, SMEM partial reduction).
// P2: 12x12 Gram matrices -> scalar recursion (warp 0) -> per-element rebuild.
// P3: H = H0 + S^T A + Un^T S rank-24 GEMM from SMEM (3 x 64-row blocks).

#define NN 192
#define TT 12
#define BE 256

typedef unsigned long long u64;

__device__ __forceinline__ u64 fma2(u64 a, u64 b, u64 c) {
    u64 d; asm("fma.rn.f32x2 %0, %1, %2, %3;" : "=l"(d) : "l"(a), "l"(b), "l"(c));
    return d;
}
__device__ __forceinline__ u64 add2(u64 a, u64 b) {
    u64 d; asm("add.rn.f32x2 %0, %1, %2;" : "=l"(d) : "l"(a), "l"(b));
    return d;
}
__device__ __forceinline__ u64 pack2(float lo, float hi) {
    u64 d; asm("mov.b64 %0, {%1, %2};" : "=l"(d) : "f"(lo), "f"(hi));
    return d;
}
__device__ __forceinline__ void unpack2(u64 v, float& lo, float& hi) {
    asm("mov.b64 {%0, %1}, %2;" : "=f"(lo), "=f"(hi) : "l"(v));
}

// ---- SMEM byte offsets ----
#define O_SS 0         // float [12][192]
#define O_SY 9216
#define O_SU 18432
#define O_SV 27648
#define O_G1 36864     // float [12][12]
#define O_GW 37440
#define O_CU 38016
#define O_CV 38592
#define O_CB 39168
#define O_C1 39744     // float [12]
#define O_C2 39792
#define O_UN 39840     // phase union, 61696 bytes
// p1 view:  YP  = O_UN          u64   [192][8]   12288
//           ST2 = O_UN+12288    float [32][194]  24832   (st2[jj][i] = H0[i][j0+jj])
//           T2  = O_UN+37120    float [32][192]  24576   (t2 [jj][i] = H0[j0+jj][i])
// red view: PU  = O_UN          u64   [2][192][8] 24576
//           PV  = O_UN+24576    u64   [2][192][8] 24576
// p3 view:  SA  = O_UN          float [12][192]   9216
//           SUN = O_UN+9216     float [12][192]   9216
#define SMEM_TOTAL (39840 + 61696)

__global__ void __launch_bounds__(192, 2)
bfgs_fused(const float* __restrict__ H0g,
           const float* __restrict__ steps,
           const float* __restrict__ dgs,
           float* __restrict__ out)
{
    extern __shared__ char smraw[];
    float* sS = (float*)(smraw + O_SS);
    float* sY = (float*)(smraw + O_SY);
    float* sU = (float*)(smraw + O_SU);
    float* sV = (float*)(smraw + O_SV);
    float* g1 = (float*)(smraw + O_G1);
    float* gw = (float*)(smraw + O_GW);
    float* cu = (float*)(smraw + O_CU);
    float* cv = (float*)(smraw + O_CV);
    float* cb = (float*)(smraw + O_CB);
    float* c1s = (float*)(smraw + O_C1);
    float* c2s = (float*)(smraw + O_C2);
    u64*   Yp  = (u64*)  (smraw + O_UN);
    float* st2 = (float*)(smraw + O_UN + 12288);
    float* t2  = (float*)(smraw + O_UN + 37120);
    u64*   PU  = (u64*)  (smraw + O_UN);
    u64*   PV  = (u64*)  (smraw + O_UN + 24576);
    float* sA  = (float*)(smraw + O_UN);
    float* sUn = (float*)(smraw + O_UN + 9216);

    const int tid = threadIdx.x;
    const int be  = blockIdx.x;

    // ---- Load S, Y ----
    for (int idx = tid; idx < TT * NN / 4; idx += 192) {
        int e = idx * 4;
        int k = e / NN, j = e % NN;
        *(float4*)&sS[k * NN + j] = *(const float4*)&steps[(size_t)(k * BE + be) * NN + j];
        *(float4*)&sY[k * NN + j] = *(const float4*)&dgs  [(size_t)(k * BE + be) * NN + j];
    }
    __syncthreads();

    // ---- Pack Y into t-pairs: Yp[j][p] = (Y[2p][j], Y[2p+1][j]) ----
    {
        int j = tid;
        #pragma unroll
        for (int p = 0; p < 6; p++)
            Yp[j * 8 + p] = pack2(sY[(2 * p) * NN + j], sY[(2 * p + 1) * NN + j]);
    }

    // ---- P1: tiled matvecs. thread = (cg columns i0,i0+1) x (jh half of j) ----
    const int cg = tid % 96, jh = tid / 96;
    const int i0 = cg * 2;
    u64 aU[2][6], aV[2][6];
    #pragma unroll
    for (int c = 0; c < 2; c++)
        #pragma unroll
        for (int p = 0; p < 6; p++) { aU[c][p] = 0ull; aV[c][p] = 0ull; }

    for (int jt = 0; jt < 6; jt++) {
        const int j0 = jt * 32;
        __syncthreads();
        // t2[jj][i] = H0[j0+jj][i] : coalesced float4 rows
        #pragma unroll
        for (int n = 0; n < 8; n++) {
            int fi = n * 192 + tid;
            int row = fi / 48, c4 = (fi % 48) * 4;
            *(float4*)&t2[row * NN + c4] =
                *(const float4*)&H0g[(size_t)(j0 + row) * NN + c4];
        }
        // st2[jj][i] = H0[i][j0+jj] : read coalesced float4, scatter transposed
        #pragma unroll
        for (int n = 0; n < 8; n++) {
            int fi = n * 192 + tid;
            int r = fi >> 3, q = fi & 7;
            float4 h4 = *(const float4*)&H0g[(size_t)r * NN + j0 + 4 * q];
            st2[(4 * q + 0) * 194 + r] = h4.x;
            st2[(4 * q + 1) * 194 + r] = h4.y;
            st2[(4 * q + 2) * 194 + r] = h4.z;
            st2[(4 * q + 3) * 194 + r] = h4.w;
        }
        __syncthreads();

        #pragma unroll
        for (int jj16 = 0; jj16 < 16; jj16++) {
            const int jj = jh * 16 + jj16;
            const int j  = j0 + jj;
            ulonglong2 y01 = *(const ulonglong2*)&Yp[j * 8 + 0];
            ulonglong2 y23 = *(const ulonglong2*)&Yp[j * 8 + 2];
            ulonglong2 y45 = *(const ulonglong2*)&Yp[j * 8 + 4];
            u64 yv[6] = {y01.x, y01.y, y23.x, y23.y, y45.x, y45.y};
            float2 hu = *(const float2*)&st2[jj * 194 + i0];   // H0[i0..i0+1][j]
            float2 hv = *(const float2*)&t2[jj * NN + i0];     // H0[j][i0..i0+1]
            u64 hu2[2] = {pack2(hu.x, hu.x), pack2(hu.y, hu.y)};
            u64 hv2[2] = {pack2(hv.x, hv.x), pack2(hv.y, hv.y)};
            #pragma unroll
            for (int p = 0; p < 6; p++) {
                aU[0][p] = fma2(hu2[0], yv[p], aU[0][p]);
                aU[1][p] = fma2(hu2[1], yv[p], aU[1][p]);
                aV[0][p] = fma2(hv2[0], yv[p], aV[0][p]);
                aV[1][p] = fma2(hv2[1], yv[p], aV[1][p]);
            }
        }
    }
    __syncthreads();   // p1 tiles dead -> safe to alias with partials

    // ---- partial write + reduction into sU, sV ----
    #pragma unroll
    for (int c = 0; c < 2; c++)
        #pragma unroll
        for (int p = 0; p < 6; p++) {
            PU[((size_t)jh * NN + i0 + c) * 8 + p] = aU[c][p];
            PV[((size_t)jh * NN + i0 + c) * 8 + p] = aV[c][p];
        }
    __syncthreads();
    {
        int i = tid;
        #pragma unroll
        for (int p = 0; p < 6; p++) {
            u64 su = add2(PU[(size_t)i * 8 + p], PU[((size_t)NN + i) * 8 + p]);
            u64 sv = add2(PV[(size_t)i * 8 + p], PV[((size_t)NN + i) * 8 + p]);
            float lo, hi;
            unpack2(su, lo, hi);
            sU[(2 * p) * NN + i] = lo; sU[(2 * p + 1) * NN + i] = hi;
            unpack2(sv, lo, hi);
            sV[(2 * p) * NN + i] = lo; sV[(2 * p + 1) * NN + i] = hi;
        }
    }
    __syncthreads();

    // ---- Grams: G1 = S Y^T, W = V0 Y^T (2x2 cells per thread, 72 threads) ----
    if (tid < 72) {
        int which = tid / 36;
        int cell  = tid % 36;
        int k0 = (cell / 6) * 2, t0 = (cell % 6) * 2;
        const float* P = which ? sV : sS;
        float a00 = 0.f, a01 = 0.f, a10 = 0.f, a11 = 0.f;
        for (int j = 0; j < NN; j += 4) {
            float4 p0 = *(const float4*)&P[k0 * NN + j];
            float4 p1 = *(const float4*)&P[(k0 + 1) * NN + j];
            float4 q0 = *(const float4*)&sY[t0 * NN + j];
            float4 q1 = *(const float4*)&sY[(t0 + 1) * NN + j];
            a00 += p0.x * q0.x + p0.y * q0.y + p0.z * q0.z + p0.w * q0.w;
            a01 += p0.x * q1.x + p0.y * q1.y + p0.z * q1.z + p0.w * q1.w;
            a10 += p1.x * q0.x + p1.y * q0.y + p1.z * q0.z + p1.w * q0.w;
            a11 += p1.x * q1.x + p1.y * q1.y + p1.z * q1.z + p1.w * q1.w;
        }
        float* G = which ? gw : g1;
        G[k0 * TT + t0] = a00;       G[k0 * TT + t0 + 1] = a01;
        G[(k0 + 1) * TT + t0] = a10; G[(k0 + 1) * TT + t0 + 1] = a11;
    }
    __syncthreads();

    // ---- Warp-0 scalar recursion, lane = column t ----
    if (tid < 32) {
        const int t = (tid < TT) ? tid : (TT - 1);
        float G1c[TT], Wc[TT], Wr[TT];
        float d2c[TT], d3c[TT];
        float c1v[TT], c2v[TT];
        float cuL[TT], cvL[TT], bL[TT];
        #pragma unroll
        for (int m = 0; m < TT; m++) {
            G1c[m] = g1[m * TT + t];
            Wc[m]  = gw[m * TT + t];
            Wr[m]  = gw[t * TT + m];
            cuL[m] = 0.f; cvL[m] = 0.f; bL[m] = 0.f;
        }
        #pragma unroll
        for (int k = 0; k < TT; k++) {
            if (k > 0) {
                const int m = k - 1;
                cuL[m] = c1v[m] * G1c[m] - c2v[m] * d2c[m];
                cvL[m] = c1v[m] * G1c[m] - c2v[m] * d3c[m];
                bL[m]  = -c2v[m] * G1c[m];
            }
            float x2 = Wc[k], x3 = Wr[k];
            #pragma unroll
            for (int m = 0; m < TT - 1; m++) {
                if (m < k) {
                    float cvk = __shfl_sync(0xFFFFFFFFu, cvL[m], k);
                    float cuk = __shfl_sync(0xFFFFFFFFu, cuL[m], k);
                    float bk  = __shfl_sync(0xFFFFFFFFu, bL[m],  k);
                    x2 += cvk * G1c[m] + bk * d2c[m];
                    x3 += cuk * G1c[m] + bk * d3c[m];
                }
            }
            d2c[k] = x2;
            d3c[k] = x3;
            float yHy  = __shfl_sync(0xFFFFFFFFu, x3, k);
            float sdot = __shfl_sync(0xFFFFFFFFu, G1c[k], k);
            float ic = (sdot != 0.0f) ? (1.0f / sdot) : 0.0f;
            c2v[k] = ic;
            c1v[k] = (sdot + yHy) * ic * ic;
        }
        if (tid < TT) {
            #pragma unroll
            for (int m = 0; m < TT - 1; m++) {
                cu[m * TT + t] = cuL[m];
                cv[m * TT + t] = cvL[m];
                cb[m * TT + t] = bL[m];
            }
        }
        if (tid == 0) {
            #pragma unroll
            for (int m = 0; m < TT; m++) { c1s[m] = c1v[m]; c2s[m] = c2v[m]; }
        }
    }
    __syncthreads();

    // ---- Per-element rebuild -> A, Un into SMEM (aliases dead partials) ----
    {
        const int i = tid;
        float s[TT], u[TT], v[TT];
        #pragma unroll
        for (int k = 0; k < TT; k++) {
            s[k] = sS[k * NN + i];
            u[k] = sU[k * NN + i];
            v[k] = sV[k * NN + i];
        }
        #pragma unroll
        for (int t = 0; t < TT; t++) {
            #pragma unroll
            for (int k = 0; k < TT - 1; k++) {
                if (k < t) {
                    float bb = cb[k * TT + t];
                    u[t] += cu[k * TT + t] * s[k] + bb * u[k];
                    v[t] += cv[k * TT + t] * s[k] + bb * v[k];
                }
            }
            float c1 = c1s[t], c2 = c2s[t];
            sA [t * NN + i] = c1 * s[t] - c2 * v[t];
            sUn[t * NN + i] = -c2 * u[t];
        }
    }
    __syncthreads();

    // ---- P3: H = H0 + S^T A + Un^T S, rank-24, 3 x 64-row blocks ----
    const int cgE = tid >> 3, rg = tid & 7;
    const int c0  = cgE * 8;
    const int lr0 = rg * 8;
    float* ob = out + (size_t)be * NN * NN;

    for (int rblk = 0; rblk < NN; rblk += 64) {
        const int grow = rblk + lr0;
        u64 acc[8][4];
        #pragma unroll
        for (int r = 0; r < 8; r++) {
            ulonglong2 h01 = *(const ulonglong2*)&H0g[(size_t)(grow + r) * NN + c0];
            ulonglong2 h23 = *(const ulonglong2*)&H0g[(size_t)(grow + r) * NN + c0 + 4];
            acc[r][0] = h01.x; acc[r][1] = h01.y; acc[r][2] = h23.x; acc[r][3] = h23.y;
        }
        #pragma unroll
        for (int k = 0; k < TT; k++) {
            ulonglong2 a01 = *(ulonglong2*)&sA[k * NN + c0];
            ulonglong2 a23 = *(ulonglong2*)&sA[k * NN + c0 + 4];
            ulonglong2 s01 = *(ulonglong2*)&sS[k * NN + c0];
            ulonglong2 s23 = *(ulonglong2*)&sS[k * NN + c0 + 4];
            u64 av[4] = {a01.x, a01.y, a23.x, a23.y};
            u64 sv[4] = {s01.x, s01.y, s23.x, s23.y};
            float4 sr0 = *(float4*)&sS[k * NN + grow];
            float4 sr1 = *(float4*)&sS[k * NN + grow + 4];
            float4 ur0 = *(float4*)&sUn[k * NN + grow];
            float4 ur1 = *(float4*)&sUn[k * NN + grow + 4];
            float srow[8] = {sr0.x, sr0.y, sr0.z, sr0.w, sr1.x, sr1.y, sr1.z, sr1.w};
            float urow[8] = {ur0.x, ur0.y, ur0.z, ur0.w, ur1.x, ur1.y, ur1.z, ur1.w};
            #pragma unroll
            for (int r = 0; r < 8; r++) {
                u64 s2 = pack2(srow[r], srow[r]);
                u64 u2 = pack2(urow[r], urow[r]);
                #pragma unroll
                for (int c = 0; c < 4; c++) {
                    acc[r][c] = fma2(s2, av[c], acc[r][c]);
                    acc[r][c] = fma2(u2, sv[c], acc[r][c]);
                }
            }
        }
        #pragma unroll
        for (int r = 0; r < 8; r++) {
            *(ulonglong2*)&ob[(size_t)(grow + r) * NN + c0] =
                make_ulonglong2(acc[r][0], acc[r][1]);
            *(ulonglong2*)&ob[(size_t)(grow + r) * NN + c0 + 4] =
                make_ulonglong2(acc[r][2], acc[r][3]);
        }
    }
}

extern "C" void kernel_launch(void* const* d_in, const int* in_sizes, int n_in,
                              void* d_out, int out_size) {
    const float* H0    = (const float*)d_in[0];   // inv_hessian [192,192]
    const float* steps = (const float*)d_in[1];   // [12,8,32,192]
    const float* dgs   = (const float*)d_in[2];   // [12,8,32,192]
    float* out = (float*)d_out;                   // [8,32,192,192]

    cudaFuncSetAttribute(bfgs_fused,
                         cudaFuncAttributeMaxDynamicSharedMemorySize, SMEM_TOTAL);
    bfgs_fused<<<BE, 192, SMEM_TOTAL>>>(H0, steps, dgs, out);
}